// round 1
// baseline (speedup 1.0000x reference)
#include <cuda_runtime.h>
#include <math.h>

// Problem constants (fixed by reference)
#define IMG_W 128
#define IMG_H 128
#define TILE_W 16
#define TILE_H 8
#define NTHREADS 128      // one thread per tile pixel
#define CHUNK 1024        // gaussians tested per block iteration (8 per thread)
#define MAXBN 32768       // capacity for B*N param records

// Per-(batch,gaussian) precomputed params.
// g_p1 = {proj_x, proj_y, K2 = -1/(2*var*ln2), log2(opacity)}
// g_p2 = {color_r, color_g, color_b, 0}
static __device__ float4 g_p1[MAXBN];
static __device__ float4 g_p2[MAXBN];

__global__ void prep_kernel(const float* __restrict__ pos,
                            const float* __restrict__ col,
                            const float* __restrict__ opa,
                            const float* __restrict__ sca,
                            const float* __restrict__ qv,
                            const float* __restrict__ tv,
                            int N, int B) {
    int i = blockIdx.x * blockDim.x + threadIdx.x;
    if (i >= N * B) return;
    int b = i / N;
    int n = i - b * N;

    // Quaternion -> rotation (normalized), matching reference exactly.
    float qw = qv[b * 4 + 0], qx = qv[b * 4 + 1], qy = qv[b * 4 + 2], qz = qv[b * 4 + 3];
    float inv = rsqrtf(qw * qw + qx * qx + qy * qy + qz * qz);
    qw *= inv; qx *= inv; qy *= inv; qz *= inv;
    float R00 = 1.f - 2.f * (qy * qy + qz * qz), R01 = 2.f * (qx * qy - qz * qw), R02 = 2.f * (qx * qz + qy * qw);
    float R10 = 2.f * (qx * qy + qz * qw), R11 = 1.f - 2.f * (qx * qx + qz * qz), R12 = 2.f * (qy * qz - qx * qw);
    float R20 = 2.f * (qx * qz - qy * qw), R21 = 2.f * (qy * qz + qx * qw), R22 = 1.f - 2.f * (qx * qx + qy * qy);

    float px = pos[n * 3 + 0], py = pos[n * 3 + 1], pz = pos[n * 3 + 2];
    float cxm = R00 * px + R01 * py + R02 * pz + tv[b * 3 + 0];
    float cym = R10 * px + R11 * py + R12 * pz + tv[b * 3 + 1];
    float czm = R20 * px + R21 * py + R22 * pz + tv[b * 3 + 2];

    float projx = cxm / czm * 500.0f + 64.0f;
    float projy = cym / czm * 500.0f + 64.0f;

    float s = sca[n];
    float var = s * s;
    float K2 = -0.72134752044f / var;             // -1/(2*var*ln2): exp(-.5 d2/var) = 2^(K2*d2)
    float lo = log2f(fmaxf(opa[n], 1e-30f));      // fold opacity into the exponent

    // Sanitize: non-finite projections (z ~ 0) must be culled cleanly, never NaN.
    if (!isfinite(projx) || !isfinite(projy)) { projx = 3e18f; projy = 3e18f; }

    g_p1[i] = make_float4(projx, projy, K2, lo);
    g_p2[i] = make_float4(col[n * 3 + 0], col[n * 3 + 1], col[n * 3 + 2], 0.f);
}

__global__ void __launch_bounds__(NTHREADS)
render_kernel(float* __restrict__ out, int N) {
    __shared__ float4 sP1[CHUNK];
    __shared__ float4 sP2[CHUNK];
    __shared__ int    sIdx[CHUNK];
    __shared__ int    sOff[NTHREADS];
    __shared__ int    sCnt;

    const int t  = threadIdx.x;
    const int b  = blockIdx.z;
    const int x0 = blockIdx.x * TILE_W;
    const int y0 = blockIdx.y * TILE_H;
    const int px = x0 + (t & (TILE_W - 1));
    const int py = y0 + (t >> 4);
    const float xf = (float)px;
    const float yf = (float)py;
    const int gb = b * N;

    const float fx0 = (float)x0, fx1 = (float)(x0 + TILE_W - 1);
    const float fy0 = (float)y0, fy1 = (float)(y0 + TILE_H - 1);

    float accR = 0.f, accG = 0.f, accB = 0.f, accD = 0.f;

    for (int base = 0; base < N; base += CHUNK) {
        // ---- Phase 1: test (deterministic flag collection, coalesced reads) ----
        unsigned keepmask = 0;
        int k = 0;
        #pragma unroll
        for (int j = 0; j < CHUNK / NTHREADS; ++j) {
            int i = base + t + j * NTHREADS;
            if (i < N) {
                float4 p = g_p1[gb + i];
                float dx = fmaxf(0.f, fmaxf(fx0 - p.x, p.x - fx1));
                float dy = fmaxf(0.f, fmaxf(fy0 - p.y, p.y - fy1));
                float amax = fmaf(p.z, fmaf(dx, dx, dy * dy), p.w);
                if (amax > -60.f) { keepmask |= (1u << j); ++k; }
            }
        }
        sOff[t] = k;
        __syncthreads();

        // ---- Phase 2: exclusive scan (serial by t0; 128 adds, negligible) ----
        if (t == 0) {
            int run = 0;
            #pragma unroll 8
            for (int u = 0; u < NTHREADS; ++u) { int c = sOff[u]; sOff[u] = run; run += c; }
            sCnt = run;
        }
        __syncthreads();

        // ---- Phase 3: deterministic compaction + gather into shared ----
        int wpos = sOff[t];
        #pragma unroll
        for (int j = 0; j < CHUNK / NTHREADS; ++j) {
            if (keepmask & (1u << j)) sIdx[wpos++] = base + t + j * NTHREADS;
        }
        __syncthreads();

        const int cnt = sCnt;
        for (int j = t; j < cnt; j += NTHREADS) {
            int gi = gb + sIdx[j];
            sP1[j] = g_p1[gi];
            sP2[j] = g_p2[gi];
        }
        __syncthreads();

        // ---- Phase 4: accumulate over survivors (broadcast LDS.128) ----
        #pragma unroll 4
        for (int j = 0; j < cnt; ++j) {
            float4 p1 = sP1[j];
            float4 p2 = sP2[j];
            float dx = xf - p1.x;
            float dy = yf - p1.y;
            float d2 = fmaf(dx, dx, dy * dy);
            float e  = exp2f(fmaf(p1.z, d2, p1.w));
            accD += e;
            accR = fmaf(e, p2.x, accR);
            accG = fmaf(e, p2.y, accG);
            accB = fmaf(e, p2.z, accB);
        }
        __syncthreads();
    }

    // den = sum(w) + EPS ; img = num / den  (den >= EPS always since w >= 0)
    float invd = 1.0f / (accD + 1e-8f);
    int o = ((b * 3 + 0) * IMG_H + py) * IMG_W + px;
    out[o]                     = accR * invd;
    out[o + IMG_H * IMG_W]     = accG * invd;
    out[o + 2 * IMG_H * IMG_W] = accB * invd;
}

extern "C" void kernel_launch(void* const* d_in, const int* in_sizes, int n_in,
                              void* d_out, int out_size) {
    const float* positions = (const float*)d_in[0];  // (N,3)
    const float* colors    = (const float*)d_in[1];  // (N,3)
    const float* opacities = (const float*)d_in[2];  // (N,1)
    const float* scales    = (const float*)d_in[3];  // (N,1)
    const float* qvec      = (const float*)d_in[4];  // (B,4)
    const float* tvec      = (const float*)d_in[5];  // (B,3)

    int N = in_sizes[0] / 3;
    int B = in_sizes[4] / 4;
    if (N * B > MAXBN) return;  // capacity guard (problem is N=4096, B=2)

    int total = N * B;
    prep_kernel<<<(total + 255) / 256, 256>>>(positions, colors, opacities, scales,
                                              qvec, tvec, N, B);

    dim3 grid(IMG_W / TILE_W, IMG_H / TILE_H, B);
    render_kernel<<<grid, NTHREADS>>>((float*)d_out, N);
}

// round 2
// speedup vs baseline: 1.4125x; 1.4125x over previous
#include <cuda_runtime.h>
#include <math.h>

// Problem constants (fixed by reference)
#define IMG_W 128
#define IMG_H 128
#define TILE  16          // 16x16 pixel tiles -> 8*8*B = 128 blocks (single wave)
#define NT    256         // one thread per tile pixel
#define NWARP (NT / 32)
#define MAXN  8192        // capacity for per-tile survivor index list (N <= MAXN)
#define MAXBN 32768       // capacity for B*N param records

// Per-(batch,gaussian) precomputed params.
// g_p1 = {proj_x, proj_y, K2 = -1/(2*var*ln2), log2(opacity)}
// g_p2 = {color_r, color_g, color_b, 0}
static __device__ float4 g_p1[MAXBN];
static __device__ float4 g_p2[MAXBN];

__global__ void prep_kernel(const float* __restrict__ pos,
                            const float* __restrict__ col,
                            const float* __restrict__ opa,
                            const float* __restrict__ sca,
                            const float* __restrict__ qv,
                            const float* __restrict__ tv,
                            int N, int B) {
    int i = blockIdx.x * blockDim.x + threadIdx.x;
    if (i >= N * B) return;
    int b = i / N;
    int n = i - b * N;

    // Quaternion -> rotation (normalized), matching reference exactly.
    float qw = qv[b * 4 + 0], qx = qv[b * 4 + 1], qy = qv[b * 4 + 2], qz = qv[b * 4 + 3];
    float inv = rsqrtf(qw * qw + qx * qx + qy * qy + qz * qz);
    qw *= inv; qx *= inv; qy *= inv; qz *= inv;
    float R00 = 1.f - 2.f * (qy * qy + qz * qz), R01 = 2.f * (qx * qy - qz * qw), R02 = 2.f * (qx * qz + qy * qw);
    float R10 = 2.f * (qx * qy + qz * qw), R11 = 1.f - 2.f * (qx * qx + qz * qz), R12 = 2.f * (qy * qz - qx * qw);
    float R20 = 2.f * (qx * qz - qy * qw), R21 = 2.f * (qy * qz + qx * qw), R22 = 1.f - 2.f * (qx * qx + qy * qy);

    float px = pos[n * 3 + 0], py = pos[n * 3 + 1], pz = pos[n * 3 + 2];
    float cxm = R00 * px + R01 * py + R02 * pz + tv[b * 3 + 0];
    float cym = R10 * px + R11 * py + R12 * pz + tv[b * 3 + 1];
    float czm = R20 * px + R21 * py + R22 * pz + tv[b * 3 + 2];

    float projx = cxm / czm * 500.0f + 64.0f;
    float projy = cym / czm * 500.0f + 64.0f;

    float s = sca[n];
    float var = s * s;
    float K2 = -0.72134752044f / var;             // exp(-.5 d2/var) = 2^(K2*d2)
    float lo = log2f(fmaxf(opa[n], 1e-30f));      // fold opacity into the exponent

    // Sanitize: non-finite projections (z ~ 0) must be culled cleanly, never NaN.
    if (!isfinite(projx) || !isfinite(projy)) { projx = 3e18f; projy = 3e18f; }

    g_p1[i] = make_float4(projx, projy, K2, lo);
    g_p2[i] = make_float4(col[n * 3 + 0], col[n * 3 + 1], col[n * 3 + 2], 0.f);
}

__global__ void __launch_bounds__(NT)
render_kernel(float* __restrict__ out, int N) {
    __shared__ int sIdx[MAXN];     // survivor gaussian indices (local, 0..N-1)
    __shared__ int sWarp[NWARP];   // per-warp survivor counts

    const int t    = threadIdx.x;
    const int lane = t & 31;
    const int wid  = t >> 5;
    const int b    = blockIdx.z;
    const int x0   = blockIdx.x * TILE;
    const int y0   = blockIdx.y * TILE;
    const int px   = x0 + (t & (TILE - 1));
    const int py   = y0 + (t >> 4);
    const float xf = (float)px;
    const float yf = (float)py;
    const int gb   = b * N;

    const float fx0 = (float)x0, fx1 = (float)(x0 + TILE - 1);
    const float fy0 = (float)y0, fy1 = (float)(y0 + TILE - 1);

    const float4* __restrict__ P1 = g_p1 + gb;
    const float4* __restrict__ P2 = g_p2 + gb;

    // ---- Phase 1: conservative tile-bbox test, one pass over all N ----
    unsigned keep = 0;
    int k = 0;
    #pragma unroll 4
    for (int j = 0; j * NT + t < N; ++j) {
        float4 p = P1[j * NT + t];
        float dx = fmaxf(0.f, fmaxf(fx0 - p.x, p.x - fx1));
        float dy = fmaxf(0.f, fmaxf(fy0 - p.y, p.y - fy1));
        float amax = fmaf(p.z, fmaf(dx, dx, dy * dy), p.w);
        if (amax > -60.f) { keep |= (1u << j); ++k; }
    }

    // ---- Phase 2: warp-shuffle inclusive scan + tiny cross-warp combine ----
    int incl = k;
    #pragma unroll
    for (int o = 1; o < 32; o <<= 1) {
        int v = __shfl_up_sync(0xffffffffu, incl, o);
        if (lane >= o) incl += v;
    }
    if (lane == 31) sWarp[wid] = incl;
    __syncthreads();

    int warpBase = 0, cnt = 0;
    #pragma unroll
    for (int w = 0; w < NWARP; ++w) {
        int c = sWarp[w];
        if (w < wid) warpBase += c;
        cnt += c;
    }
    int wpos = warpBase + incl - k;

    // ---- Phase 3: deterministic compaction of indices ----
    #pragma unroll 4
    for (int j = 0; j * NT + t < N; ++j) {
        if (keep & (1u << j)) sIdx[wpos++] = j * NT + t;
    }
    __syncthreads();

    // ---- Phase 4: accumulate over survivors (broadcast LDG.128 from L1/L2) ----
    float accR = 0.f, accG = 0.f, accB = 0.f, accD = 0.f;
    #pragma unroll 4
    for (int j = 0; j < cnt; ++j) {
        int gi = sIdx[j];
        float4 p1 = P1[gi];
        float4 p2 = P2[gi];
        float dx = xf - p1.x;
        float dy = yf - p1.y;
        float d2 = fmaf(dx, dx, dy * dy);
        float e  = exp2f(fmaf(p1.z, d2, p1.w));
        accD += e;
        accR = fmaf(e, p2.x, accR);
        accG = fmaf(e, p2.y, accG);
        accB = fmaf(e, p2.z, accB);
    }

    // den = sum(w) + EPS ; img = num / den  (den >= EPS always since w >= 0)
    float invd = 1.0f / (accD + 1e-8f);
    int o = ((b * 3 + 0) * IMG_H + py) * IMG_W + px;
    out[o]                     = accR * invd;
    out[o + IMG_H * IMG_W]     = accG * invd;
    out[o + 2 * IMG_H * IMG_W] = accB * invd;
}

extern "C" void kernel_launch(void* const* d_in, const int* in_sizes, int n_in,
                              void* d_out, int out_size) {
    const float* positions = (const float*)d_in[0];  // (N,3)
    const float* colors    = (const float*)d_in[1];  // (N,3)
    const float* opacities = (const float*)d_in[2];  // (N,1)
    const float* scales    = (const float*)d_in[3];  // (N,1)
    const float* qvec      = (const float*)d_in[4];  // (B,4)
    const float* tvec      = (const float*)d_in[5];  // (B,3)

    int N = in_sizes[0] / 3;
    int B = in_sizes[4] / 4;
    if (N * B > MAXBN || N > MAXN) return;  // capacity guard (problem is N=4096, B=2)

    int total = N * B;
    prep_kernel<<<(total + 255) / 256, 256>>>(positions, colors, opacities, scales,
                                              qvec, tvec, N, B);

    dim3 grid(IMG_W / TILE, IMG_H / TILE, B);
    render_kernel<<<grid, NT>>>((float*)d_out, N);
}

// round 4
// speedup vs baseline: 1.4169x; 1.0031x over previous
#include <cuda_runtime.h>
#include <math.h>

// Problem constants (fixed by reference)
#define IMG_W 128
#define IMG_H 128
#define TILE  16          // 16x16 pixel tiles -> 8*8*B = 128 blocks (single wave)
#define PIX   256         // pixels per tile
#define SPLIT 4           // gaussian-axis split within a block
#define NT    (PIX * SPLIT)   // 1024 threads
#define MAXN  8192        // survivor index capacity (N <= MAXN, fits u16)
#define MAXBN 32768       // capacity for B*N param records

// Per-(batch,gaussian) precomputed params.
// g_p1 = {proj_x, proj_y, K2 = -1/(2*var*ln2), log2(opacity)}
// g_p2 = {color_r, color_g, color_b, 0}
static __device__ float4 g_p1[MAXBN];
static __device__ float4 g_p2[MAXBN];

__global__ void prep_kernel(const float* __restrict__ pos,
                            const float* __restrict__ col,
                            const float* __restrict__ opa,
                            const float* __restrict__ sca,
                            const float* __restrict__ qv,
                            const float* __restrict__ tv,
                            int N, int B) {
    int i = blockIdx.x * blockDim.x + threadIdx.x;
    if (i >= N * B) return;
    int b = i / N;
    int n = i - b * N;

    // Quaternion -> rotation (normalized), matching reference exactly.
    float qw = qv[b * 4 + 0], qx = qv[b * 4 + 1], qy = qv[b * 4 + 2], qz = qv[b * 4 + 3];
    float inv = rsqrtf(qw * qw + qx * qx + qy * qy + qz * qz);
    qw *= inv; qx *= inv; qy *= inv; qz *= inv;
    float R00 = 1.f - 2.f * (qy * qy + qz * qz), R01 = 2.f * (qx * qy - qz * qw), R02 = 2.f * (qx * qz + qy * qw);
    float R10 = 2.f * (qx * qy + qz * qw), R11 = 1.f - 2.f * (qx * qx + qz * qz), R12 = 2.f * (qy * qz - qx * qw);
    float R20 = 2.f * (qx * qz - qy * qw), R21 = 2.f * (qy * qz + qx * qw), R22 = 1.f - 2.f * (qx * qx + qy * qy);

    float px = pos[n * 3 + 0], py = pos[n * 3 + 1], pz = pos[n * 3 + 2];
    float cxm = R00 * px + R01 * py + R02 * pz + tv[b * 3 + 0];
    float cym = R10 * px + R11 * py + R12 * pz + tv[b * 3 + 1];
    float czm = R20 * px + R21 * py + R22 * pz + tv[b * 3 + 2];

    float projx = cxm / czm * 500.0f + 64.0f;
    float projy = cym / czm * 500.0f + 64.0f;

    float s = sca[n];
    float var = s * s;
    float K2 = -0.72134752044f / var;             // exp(-.5 d2/var) = 2^(K2*d2)
    float lo = log2f(fmaxf(opa[n], 1e-30f));      // fold opacity into the exponent

    // Sanitize: non-finite projections (z ~ 0) must be culled cleanly, never NaN.
    if (!isfinite(projx) || !isfinite(projy)) { projx = 3e18f; projy = 3e18f; }

    g_p1[i] = make_float4(projx, projy, K2, lo);
    g_p2[i] = make_float4(col[n * 3 + 0], col[n * 3 + 1], col[n * 3 + 2], 0.f);
}

__global__ void __launch_bounds__(NT)
render_kernel(float* __restrict__ out, int N) {
    __shared__ unsigned short sIdx[MAXN + SPLIT]; // survivor indices (u16), by sub
    __shared__ int    sWarp[NT / 32];             // per-warp survivor counts
    __shared__ float4 sAcc[NT];                   // per-(sub,pixel) partials

    const int t    = threadIdx.x;
    const int lane = t & 31;
    const int wid  = t >> 5;                // 0..31
    const int sub  = wid >> 3;              // 0..3 : gaussian-axis slice
    const int wsub = wid & 7;               // warp-in-sub 0..7
    const int pt   = t & (PIX - 1);         // pixel-in-tile 0..255
    const int b    = blockIdx.z;
    const int x0   = blockIdx.x * TILE;
    const int y0   = blockIdx.y * TILE;
    const float xf = (float)(x0 + (pt & (TILE - 1)));
    const float yf = (float)(y0 + (pt >> 4));

    const float fx0 = (float)x0, fx1 = (float)(x0 + TILE - 1);
    const float fy0 = (float)y0, fy1 = (float)(y0 + TILE - 1);

    const float4* __restrict__ P1 = g_p1 + b * N;
    const float4* __restrict__ P2 = g_p2 + b * N;

    // This sub's gaussian range and survivor-list region.
    const int s0   = (int)(((long long)sub * N) / SPLIT);
    const int s1   = (int)(((long long)(sub + 1) * N) / SPLIT);
    const int ibase = s0 + sub;             // sIdx region start (cap N/SPLIT+1 each)

    // ---- Phase 1: conservative tile-bbox test over this sub's slice ----
    unsigned keep = 0;
    int k = 0, j = 0;
    #pragma unroll 4
    for (int g = s0 + pt; g < s1; g += PIX, ++j) {
        float4 p = P1[g];
        float dx = fmaxf(0.f, fmaxf(fx0 - p.x, p.x - fx1));
        float dy = fmaxf(0.f, fmaxf(fy0 - p.y, p.y - fy1));
        float amax = fmaf(p.z, fmaf(dx, dx, dy * dy), p.w);
        if (amax > -60.f) { keep |= (1u << j); ++k; }
    }

    // ---- Phase 2: warp scan + per-sub 8-warp combine ----
    int incl = k;
    #pragma unroll
    for (int o = 1; o < 32; o <<= 1) {
        int v = __shfl_up_sync(0xffffffffu, incl, o);
        if (lane >= o) incl += v;
    }
    if (lane == 31) sWarp[wid] = incl;
    __syncthreads();

    int warpBase = 0, cnt = 0;
    #pragma unroll
    for (int w = 0; w < 8; ++w) {
        int c = sWarp[sub * 8 + w];
        if (w < wsub) warpBase += c;
        cnt += c;
    }
    int wpos = ibase + warpBase + incl - k;

    // ---- Phase 3: deterministic compaction of survivor indices ----
    j = 0;
    #pragma unroll 4
    for (int g = s0 + pt; g < s1; g += PIX, ++j) {
        if (keep & (1u << j)) sIdx[wpos++] = (unsigned short)g;
    }
    __syncthreads();

    // ---- Phase 4: accumulate this sub's survivors for this pixel ----
    float accR = 0.f, accG = 0.f, accB = 0.f, accD = 0.f;
    #pragma unroll 4
    for (int i = 0; i < cnt; ++i) {
        int gi = (int)sIdx[ibase + i];
        float4 p1 = P1[gi];          // broadcast LDG.128 (L1-resident after first warp)
        float4 p2 = P2[gi];
        float dx = xf - p1.x;
        float dy = yf - p1.y;
        float d2 = fmaf(dx, dx, dy * dy);
        float e  = exp2f(fmaf(p1.z, d2, p1.w));
        accD += e;
        accR = fmaf(e, p2.x, accR);
        accG = fmaf(e, p2.y, accG);
        accB = fmaf(e, p2.z, accB);
    }
    sAcc[t] = make_float4(accR, accG, accB, accD);
    __syncthreads();

    // ---- Phase 5: fixed-order combine of the 4 sub partials, write out ----
    if (t < PIX) {
        float4 a0 = sAcc[t];
        float4 a1 = sAcc[t + PIX];
        float4 a2 = sAcc[t + 2 * PIX];
        float4 a3 = sAcc[t + 3 * PIX];
        float r  = ((a0.x + a1.x) + (a2.x + a3.x));
        float g  = ((a0.y + a1.y) + (a2.y + a3.y));
        float bl = ((a0.z + a1.z) + (a2.z + a3.z));
        float d  = ((a0.w + a1.w) + (a2.w + a3.w));
        float invd = 1.0f / (d + 1e-8f);
        int px = x0 + (t & (TILE - 1));
        int py = y0 + (t >> 4);
        int o = ((b * 3 + 0) * IMG_H + py) * IMG_W + px;
        out[o]                     = r  * invd;
        out[o + IMG_H * IMG_W]     = g  * invd;
        out[o + 2 * IMG_H * IMG_W] = bl * invd;
    }
}

extern "C" void kernel_launch(void* const* d_in, const int* in_sizes, int n_in,
                              void* d_out, int out_size) {
    const float* positions = (const float*)d_in[0];  // (N,3)
    const float* colors    = (const float*)d_in[1];  // (N,3)
    const float* opacities = (const float*)d_in[2];  // (N,1)
    const float* scales    = (const float*)d_in[3];  // (N,1)
    const float* qvec      = (const float*)d_in[4];  // (B,4)
    const float* tvec      = (const float*)d_in[5];  // (B,3)

    int N = in_sizes[0] / 3;
    int B = in_sizes[4] / 4;
    if (N * B > MAXBN || N > MAXN) return;  // capacity guard (problem is N=4096, B=2)

    int total = N * B;
    prep_kernel<<<(total + 255) / 256, 256>>>(positions, colors, opacities, scales,
                                              qvec, tvec, N, B);

    dim3 grid(IMG_W / TILE, IMG_H / TILE, B);
    render_kernel<<<grid, NT>>>((float*)d_out, N);
}